// round 5
// baseline (speedup 1.0000x reference)
#include <cuda_runtime.h>

#define TT 512
#define DIN 64
#define HH 128
#define G3 384

typedef unsigned long long u64;

// ---------- packed f32x2 helpers (halves = adjacent k) ----------
__device__ __forceinline__ u64 f2fma(u64 a, u64 b, u64 c) {
    u64 d; asm("fma.rn.f32x2 %0, %1, %2, %3;" : "=l"(d) : "l"(a), "l"(b), "l"(c)); return d;
}
__device__ __forceinline__ u64 f2add(u64 a, u64 b) {
    u64 d; asm("add.rn.f32x2 %0, %1, %2;" : "=l"(d) : "l"(a), "l"(b)); return d;
}
__device__ __forceinline__ float f2red(u64 v) {
    float lo, hi; asm("mov.b64 {%0, %1}, %2;" : "=f"(lo), "=f"(hi) : "l"(v)); return lo + hi;
}
__device__ __forceinline__ float tanh_mufu(float x) {
    float y; asm("tanh.approx.f32 %0, %1;" : "=f"(y) : "f"(x)); return y;
}
__device__ __forceinline__ float sigm(float x) {
    return __fdividef(1.0f, 1.0f + __expf(-x));
}

// ---------- device scratch ----------
__device__ float d_Whh_q[HH * G3];     // [(iq 0..7)][o 0..383][c4 0..3][k&3]
__device__ float d_dts[TT];
__device__ unsigned char d_mask[TT];

// ---------- prologue ----------
__global__ void prep_kernel(const float* __restrict__ W_hh,
                            const float* __restrict__ tp,
                            const unsigned char* __restrict__ mask_raw)
{
    int i = blockIdx.x * blockDim.x + threadIdx.x;
    if (i < HH * G3) {
        int o = i / HH, k = i % HH;
        int iq = (k & 31) >> 2, c4v = k >> 5, l4 = k & 3;
        d_Whh_q[((iq * G3 + o) * 4 + c4v) * 4 + l4] = W_hh[i];
    }
    if (i < TT) d_dts[i] = (i == 0) ? 0.01f : (tp[i] - tp[i - 1]);

    // mask dtype sniffing (uint8 vs int32/float32 marshalling)
    if (blockIdx.x == 0) {
        __shared__ int s_off4, s_f32;
        if (threadIdx.x == 0) { s_off4 = 0; s_f32 = 0; }
        __syncthreads();
        for (int k = threadIdx.x; k < TT; k += blockDim.x)
            if (mask_raw[k] != 0 && (k & 3) != 0) atomicOr(&s_off4, 1);
        for (int k = threadIdx.x; k < TT / 4; k += blockDim.x)
            if (mask_raw[4 * k + 3] == 0x3f) atomicOr(&s_f32, 1);
        __syncthreads();
        bool word = (s_off4 == 0) || (s_f32 != 0);
        const int* mi = (const int*)mask_raw;
        for (int k = threadIdx.x; k < TT; k += blockDim.x)
            d_mask[k] = word ? (unsigned char)(mi[k] != 0)
                             : (unsigned char)(mask_raw[k] != 0);
    }
}

// ---------- smem layout (bytes) ----------
#define OFF_WHH   0        // 196608
#define OFF_H     196608   // 1024 : h     [2][128]
#define OFF_HTMP  197632   // 1024 : htmp  [2][128]
#define OFF_HODE  198656   // 1024 : h_ode [2][128]
#define OFF_INP   199680   // 512  : inp   [2][64]
#define OFF_DTS   200192   // 2048
#define OFF_MASK  202240   // 512
#define SMEM_BYTES 202752

__global__ __launch_bounds__(512, 1)
void gruode_kernel(const float* __restrict__ x,
                   const float* __restrict__ W_ih,
                   const float* __restrict__ b_ih,
                   const float* __restrict__ b_hh,
                   const float* __restrict__ W_node,
                   const float* __restrict__ b_node,
                   const float* __restrict__ W_out,
                   const float* __restrict__ b_out,
                   float* __restrict__ out)
{
    extern __shared__ char smem[];
    float* Whh_s   = (float*)(smem + OFF_WHH);
    float* h_sm    = (float*)(smem + OFF_H);
    float* htmp_sm = (float*)(smem + OFF_HTMP);
    float* hode_sm = (float*)(smem + OFF_HODE);
    float* inp_sm  = (float*)(smem + OFF_INP);
    float* sdts    = (float*)(smem + OFF_DTS);
    unsigned char* smask = (unsigned char*)(smem + OFF_MASK);

    const int t   = threadIdx.x;
    const int j4  = t >> 2;       // output row (RK4 / GRU gates)
    const int c4  = t & 3;        // 4-lane k-chunk (32 k each)
    const int oo  = t >> 3;       // out-proj output
    const int cc  = t & 7;        // out-proj k-chunk (16 k each)
    const int bid = blockIdx.x;
    const int sW  = c4 >> 1;      // writer sample (lanes 0 -> s0, 2 -> s1)
    const bool isw = (c4 & 1) == 0;

    // ---- stage W_hh into smem ----
    {
        const float4* src = (const float4*)d_Whh_q;
        float4* dst = (float4*)Whh_s;
        #pragma unroll
        for (int i = 0; i < 24; i++) dst[t + 512 * i] = src[t + 512 * i];
    }
    for (int i = t; i < TT; i += 512) { sdts[i] = d_dts[i]; smask[i] = d_mask[i]; }

    // ---- register weights (k-pair packed) ----
    u64 wn2[16];                                   // W_node[j4][32c4 .. +32)
    {
        const u64* p = (const u64*)(W_node + j4 * HH + 32 * c4);
        #pragma unroll
        for (int i = 0; i < 16; i++) wn2[i] = p[i];
    }
    u64 wihr[8], wihz[8], wihn[8];                 // W_ih rows j4, 128+j4, 256+j4 ; k in [16c4,+16)
    {
        const u64* pr = (const u64*)(W_ih + (j4)          * DIN + 16 * c4);
        const u64* pz = (const u64*)(W_ih + (HH + j4)     * DIN + 16 * c4);
        const u64* pn = (const u64*)(W_ih + (2 * HH + j4) * DIN + 16 * c4);
        #pragma unroll
        for (int i = 0; i < 8; i++) { wihr[i] = pr[i]; wihz[i] = pz[i]; wihn[i] = pn[i]; }
    }
    u64 wout2[8];                                  // W_out[oo][16cc .. +16)
    {
        const u64* p = (const u64*)(W_out + oo * HH + 16 * cc);
        #pragma unroll
        for (int i = 0; i < 8; i++) wout2[i] = p[i];
    }

    // ---- biases / state ----
    const float bn  = b_node[j4];
    const float br  = b_ih[j4] + b_hh[j4];
    const float bz  = b_ih[HH + j4] + b_hh[HH + j4];
    const float bin = b_ih[2 * HH + j4];
    const float bhn = b_hh[2 * HH + j4];
    const float bout = b_out[oo];

    float lastout0 = bout, lastout1 = bout;        // out(h0=0) = b_out
    float xreg0 = 0.f, xreg1 = 0.f;
    if (cc == 0) {
        xreg0 = x[(2 * bid)     * TT * DIN + oo];
        xreg1 = x[(2 * bid + 1) * TT * DIN + oo];
    }
    float hbase = 0.f, hodev = 0.f, ksum = 0.f;
    if (t < 256) h_sm[t] = 0.f;
    __syncthreads();

    // node matvec partials (both samples, this lane's 32-k chunk)
    auto mvp = [&](const float* src, float& d0, float& d1) {
        const ulonglong2* q0 = (const ulonglong2*)(src)      + 8 * c4;
        const ulonglong2* q1 = (const ulonglong2*)(src + HH) + 8 * c4;
        u64 a0 = 0, a1 = 0, b0 = 0, b1 = 0;
        #pragma unroll
        for (int p = 0; p < 8; p++) {
            ulonglong2 v0 = q0[p], v1 = q1[p];
            a0 = f2fma(wn2[2*p],   v0.x, a0);
            a1 = f2fma(wn2[2*p+1], v0.y, a1);
            b0 = f2fma(wn2[2*p],   v1.x, b0);
            b1 = f2fma(wn2[2*p+1], v1.y, b1);
        }
        d0 = f2red(f2add(a0, a1));
        d1 = f2red(f2add(b0, b1));
    };
    // out-projection partials + 8-lane butterfly (full sums in all lanes)
    auto outproj = [&](float& o0, float& o1) {
        const ulonglong2* hq0 = (const ulonglong2*)(h_sm)      + 4 * cc;
        const ulonglong2* hq1 = (const ulonglong2*)(h_sm + HH) + 4 * cc;
        u64 a0 = 0, a1 = 0, b0 = 0, b1 = 0;
        #pragma unroll
        for (int p = 0; p < 4; p++) {
            ulonglong2 v = hq0[p], w = hq1[p];
            a0 = f2fma(wout2[2*p],   v.x, a0);
            a1 = f2fma(wout2[2*p+1], v.y, a1);
            b0 = f2fma(wout2[2*p],   w.x, b0);
            b1 = f2fma(wout2[2*p+1], w.y, b1);
        }
        o0 = f2red(f2add(a0, a1));
        o1 = f2red(f2add(b0, b1));
        #pragma unroll
        for (int m = 1; m <= 4; m <<= 1) {
            o0 += __shfl_xor_sync(0xFFFFFFFFu, o0, m);
            o1 += __shfl_xor_sync(0xFFFFFFFFu, o1, m);
        }
    };

    for (int st = 0; st < TT; st++) {
        const float dt  = sdts[st];
        const float hdt = 0.5f * dt;
        const float dt6 = dt * (1.0f / 6.0f);

        // ---- Phase A: out-proj(h_{st-1}) + inp + mv(k1), one barrier ----
        float nx0 = 0.f, nx1 = 0.f;
        if (cc == 0 && st + 1 < TT) {               // prefetch next x early
            nx0 = x[((2 * bid)     * TT + st + 1) * DIN + oo];
            nx1 = x[((2 * bid + 1) * TT + st + 1) * DIN + oo];
        }
        float d0, d1;
        mvp(h_sm, d0, d1);
        if (st) {
            float o0, o1; outproj(o0, o1);
            if (cc == 0) {
                float v0 = o0 + bout, v1 = o1 + bout;
                out[((2 * bid)     * TT + st - 1) * DIN + oo] = v0;
                out[((2 * bid + 1) * TT + st - 1) * DIN + oo] = v1;
                lastout0 = v0; lastout1 = v1;
            }
        }
        if (cc == 0) {
            bool m = (smask[st] != 0);
            inp_sm[oo]       = m ? xreg0 : lastout0;
            inp_sm[DIN + oo] = m ? xreg1 : lastout1;
            xreg0 = nx0; xreg1 = nx1;
        }
        d0 += __shfl_xor_sync(0xFFFFFFFFu, d0, 1);
        d0 += __shfl_xor_sync(0xFFFFFFFFu, d0, 2);
        d1 += __shfl_xor_sync(0xFFFFFFFFu, d1, 1);
        d1 += __shfl_xor_sync(0xFFFFFFFFu, d1, 2);
        if (isw) {
            float k = tanh_mufu((sW ? d1 : d0) + bn);
            ksum = k;
            htmp_sm[sW * HH + j4] = hbase + hdt * k;
        }
        __syncthreads();

        // ---- k2 ----
        mvp(htmp_sm, d0, d1);
        d0 += __shfl_xor_sync(0xFFFFFFFFu, d0, 1);
        d0 += __shfl_xor_sync(0xFFFFFFFFu, d0, 2);
        d1 += __shfl_xor_sync(0xFFFFFFFFu, d1, 1);
        d1 += __shfl_xor_sync(0xFFFFFFFFu, d1, 2);
        if (isw) {
            float k = tanh_mufu((sW ? d1 : d0) + bn);
            ksum += 2.f * k;
            htmp_sm[sW * HH + j4] = hbase + hdt * k;
        }
        __syncthreads();

        // ---- k3 ----
        mvp(htmp_sm, d0, d1);
        d0 += __shfl_xor_sync(0xFFFFFFFFu, d0, 1);
        d0 += __shfl_xor_sync(0xFFFFFFFFu, d0, 2);
        d1 += __shfl_xor_sync(0xFFFFFFFFu, d1, 1);
        d1 += __shfl_xor_sync(0xFFFFFFFFu, d1, 2);
        if (isw) {
            float k = tanh_mufu((sW ? d1 : d0) + bn);
            ksum += 2.f * k;
            htmp_sm[sW * HH + j4] = hbase + dt * k;
        }
        __syncthreads();

        // ---- k4 -> h_ode ----
        mvp(htmp_sm, d0, d1);
        d0 += __shfl_xor_sync(0xFFFFFFFFu, d0, 1);
        d0 += __shfl_xor_sync(0xFFFFFFFFu, d0, 2);
        d1 += __shfl_xor_sync(0xFFFFFFFFu, d1, 1);
        d1 += __shfl_xor_sync(0xFFFFFFFFu, d1, 2);
        if (isw) {
            float k = tanh_mufu((sW ? d1 : d0) + bn);
            hodev = hbase + dt6 * (ksum + k);
            hode_sm[sW * HH + j4] = hodev;
        }
        __syncthreads();

        // ---- GRU: gate partials + 4-lane butterfly + in-lane combine ----
        {
            const ulonglong2* W2 = (const ulonglong2*)Whh_s;
            const ulonglong2* H0 = (const ulonglong2*)(hode_sm)      + 8 * c4;
            const ulonglong2* H1 = (const ulonglong2*)(hode_sm + HH) + 8 * c4;
            const int base = j4 * 4 + c4;
            u64 rA = 0, rB = 0, zA = 0, zB = 0, nA = 0, nB = 0;
            #pragma unroll
            for (int iq = 0; iq < 8; iq++) {
                ulonglong2 wr = W2[base + iq * 1536];
                ulonglong2 wz = W2[base + iq * 1536 + 512];
                ulonglong2 wn = W2[base + iq * 1536 + 1024];
                ulonglong2 h0 = H0[iq], h1 = H1[iq];
                rA = f2fma(wr.x, h0.x, rA); rA = f2fma(wr.y, h0.y, rA);
                rB = f2fma(wr.x, h1.x, rB); rB = f2fma(wr.y, h1.y, rB);
                zA = f2fma(wz.x, h0.x, zA); zA = f2fma(wz.y, h0.y, zA);
                zB = f2fma(wz.x, h1.x, zB); zB = f2fma(wz.y, h1.y, zB);
                nA = f2fma(wn.x, h0.x, nA); nA = f2fma(wn.y, h0.y, nA);
                nB = f2fma(wn.x, h1.x, nB); nB = f2fma(wn.y, h1.y, nB);
            }
            const u64* in0 = (const u64*)inp_sm + 8 * c4;
            const u64* in1 = in0 + 32;
            u64 iA = 0, iB = 0;
            #pragma unroll
            for (int p = 0; p < 8; p++) {
                u64 a = in0[p], b = in1[p];
                rA = f2fma(wihr[p], a, rA);
                zA = f2fma(wihz[p], a, zA);
                iA = f2fma(wihn[p], a, iA);
                rB = f2fma(wihr[p], b, rB);
                zB = f2fma(wihz[p], b, zB);
                iB = f2fma(wihn[p], b, iB);
            }
            float fr0 = f2red(rA), fr1 = f2red(rB);
            float fz0 = f2red(zA), fz1 = f2red(zB);
            float fi0 = f2red(iA), fi1 = f2red(iB);
            float fn0 = f2red(nA), fn1 = f2red(nB);
            #pragma unroll
            for (int m = 1; m <= 2; m <<= 1) {
                fr0 += __shfl_xor_sync(0xFFFFFFFFu, fr0, m);
                fr1 += __shfl_xor_sync(0xFFFFFFFFu, fr1, m);
                fz0 += __shfl_xor_sync(0xFFFFFFFFu, fz0, m);
                fz1 += __shfl_xor_sync(0xFFFFFFFFu, fz1, m);
                fi0 += __shfl_xor_sync(0xFFFFFFFFu, fi0, m);
                fi1 += __shfl_xor_sync(0xFFFFFFFFu, fi1, m);
                fn0 += __shfl_xor_sync(0xFFFFFFFFu, fn0, m);
                fn1 += __shfl_xor_sync(0xFFFFFFFFu, fn1, m);
            }
            if (isw) {
                float fr = sW ? fr1 : fr0, fz = sW ? fz1 : fz0;
                float fi = sW ? fi1 : fi0, fn = sW ? fn1 : fn0;
                float r = sigm(fr + br);
                float z = sigm(fz + bz);
                float n = tanhf(fi + bin + r * (fn + bhn));
                float hnew = (1.f - z) * n + z * hodev;
                hbase = hnew;
                h_sm[sW * HH + j4] = hnew;
            }
        }
        __syncthreads();
    }

    // ---- final out-projection (h_511) ----
    {
        float o0, o1; outproj(o0, o1);
        if (cc == 0) {
            out[((2 * bid)     * TT + TT - 1) * DIN + oo] = o0 + bout;
            out[((2 * bid + 1) * TT + TT - 1) * DIN + oo] = o1 + bout;
        }
    }
}

extern "C" void kernel_launch(void* const* d_in, const int* in_sizes, int n_in,
                              void* d_out, int out_size)
{
    (void)in_sizes; (void)n_in; (void)out_size;
    const float* x       = (const float*)d_in[0];
    const float* tp      = (const float*)d_in[1];
    const unsigned char* mask = (const unsigned char*)d_in[2];
    const float* W_ih    = (const float*)d_in[3];
    const float* W_hh    = (const float*)d_in[4];
    const float* b_ih    = (const float*)d_in[5];
    const float* b_hh    = (const float*)d_in[6];
    const float* W_node  = (const float*)d_in[7];
    const float* b_node  = (const float*)d_in[8];
    const float* W_out   = (const float*)d_in[9];
    const float* b_out   = (const float*)d_in[10];
    float* out = (float*)d_out;

    prep_kernel<<<192, 256>>>(W_hh, tp, mask);

    cudaFuncSetAttribute(gruode_kernel,
                         cudaFuncAttributeMaxDynamicSharedMemorySize, SMEM_BYTES);
    gruode_kernel<<<128, 512, SMEM_BYTES>>>(x, W_ih, b_ih, b_hh, W_node, b_node,
                                            W_out, b_out, out);
}

// round 6
// speedup vs baseline: 1.0258x; 1.0258x over previous
#include <cuda_runtime.h>

#define TT 512
#define DIN 64
#define HH 128
#define G3 384

typedef unsigned long long u64;

// ---------- packed f32x2 helpers (halves = adjacent k) ----------
__device__ __forceinline__ u64 f2fma(u64 a, u64 b, u64 c) {
    u64 d; asm("fma.rn.f32x2 %0, %1, %2, %3;" : "=l"(d) : "l"(a), "l"(b), "l"(c)); return d;
}
__device__ __forceinline__ u64 f2add(u64 a, u64 b) {
    u64 d; asm("add.rn.f32x2 %0, %1, %2;" : "=l"(d) : "l"(a), "l"(b)); return d;
}
__device__ __forceinline__ float f2red(u64 v) {
    float lo, hi; asm("mov.b64 {%0, %1}, %2;" : "=f"(lo), "=f"(hi) : "l"(v)); return lo + hi;
}
__device__ __forceinline__ float tanh_mufu(float x) {
    float y; asm("tanh.approx.f32 %0, %1;" : "=f"(y) : "f"(x)); return y;
}
__device__ __forceinline__ float sigm(float x) {
    return __fdividef(1.0f, 1.0f + __expf(-x));
}

// ---------- device scratch ----------
__device__ float d_Whh_q[HH * G3];     // [(iq 0..7)][o 0..383][c4 0..3][k&3]
__device__ float d_dts[TT];
__device__ unsigned char d_mask[TT];

// ---------- prologue ----------
__global__ void prep_kernel(const float* __restrict__ W_hh,
                            const float* __restrict__ tp,
                            const unsigned char* __restrict__ mask_raw)
{
    int i = blockIdx.x * blockDim.x + threadIdx.x;
    if (i < HH * G3) {
        int o = i / HH, k = i % HH;
        int iq = (k & 31) >> 2, c4v = k >> 5, l4 = k & 3;
        d_Whh_q[((iq * G3 + o) * 4 + c4v) * 4 + l4] = W_hh[i];
    }
    if (i < TT) d_dts[i] = (i == 0) ? 0.01f : (tp[i] - tp[i - 1]);

    // mask dtype sniffing (uint8 vs int32/float32 marshalling)
    if (blockIdx.x == 0) {
        __shared__ int s_off4, s_f32;
        if (threadIdx.x == 0) { s_off4 = 0; s_f32 = 0; }
        __syncthreads();
        for (int k = threadIdx.x; k < TT; k += blockDim.x)
            if (mask_raw[k] != 0 && (k & 3) != 0) atomicOr(&s_off4, 1);
        for (int k = threadIdx.x; k < TT / 4; k += blockDim.x)
            if (mask_raw[4 * k + 3] == 0x3f) atomicOr(&s_f32, 1);
        __syncthreads();
        bool word = (s_off4 == 0) || (s_f32 != 0);
        const int* mi = (const int*)mask_raw;
        for (int k = threadIdx.x; k < TT; k += blockDim.x)
            d_mask[k] = word ? (unsigned char)(mi[k] != 0)
                             : (unsigned char)(mask_raw[k] != 0);
    }
}

// ---------- smem layout (bytes) ----------
#define OFF_WHH   0        // 196608
#define OFF_H     196608   // 1024 : h     [2][128]
#define OFF_HTMP  197632   // 1024 : htmp  [2][128]
#define OFF_HODE  198656   // 1024 : h_ode [2][128]
#define OFF_INP   199680   // 512  : inp   [2][64]
#define OFF_DTS   200192   // 2048
#define OFF_MASK  202240   // 512
#define SMEM_BYTES 202752

__global__ __launch_bounds__(512, 1)
void gruode_kernel(const float* __restrict__ x,
                   const float* __restrict__ W_ih,
                   const float* __restrict__ b_ih,
                   const float* __restrict__ b_hh,
                   const float* __restrict__ W_node,
                   const float* __restrict__ b_node,
                   const float* __restrict__ W_out,
                   const float* __restrict__ b_out,
                   float* __restrict__ out)
{
    extern __shared__ char smem[];
    float* Whh_s   = (float*)(smem + OFF_WHH);
    float* h_sm    = (float*)(smem + OFF_H);
    float* htmp_sm = (float*)(smem + OFF_HTMP);
    float* hode_sm = (float*)(smem + OFF_HODE);
    float* inp_sm  = (float*)(smem + OFF_INP);
    float* sdts    = (float*)(smem + OFF_DTS);
    unsigned char* smask = (unsigned char*)(smem + OFF_MASK);

    const int t   = threadIdx.x;
    const int j4  = t >> 2;       // output row (RK4 / GRU gates)
    const int c4  = t & 3;        // 4-lane k-chunk (32 k each)
    const int oo  = t >> 3;       // out-proj output
    const int cc  = t & 7;        // out-proj k-chunk (16 k each)
    const int bid = blockIdx.x;
    const int sW  = c4 >> 1;      // writer sample (lanes 0 -> s0, 2 -> s1)
    const bool isw = (c4 & 1) == 0;

    // ---- stage W_hh into smem ----
    {
        const float4* src = (const float4*)d_Whh_q;
        float4* dst = (float4*)Whh_s;
        #pragma unroll
        for (int i = 0; i < 24; i++) dst[t + 512 * i] = src[t + 512 * i];
    }
    for (int i = t; i < TT; i += 512) { sdts[i] = d_dts[i]; smask[i] = d_mask[i]; }

    // ---- register weights (k-pair packed) ----
    u64 wn2[16];                                   // W_node[j4][32c4 .. +32)
    {
        const u64* p = (const u64*)(W_node + j4 * HH + 32 * c4);
        #pragma unroll
        for (int i = 0; i < 16; i++) wn2[i] = p[i];
    }
    u64 wihr[8], wihz[8], wihn[8];                 // W_ih rows j4, 128+j4, 256+j4 ; k in [16c4,+16)
    {
        const u64* pr = (const u64*)(W_ih + (j4)          * DIN + 16 * c4);
        const u64* pz = (const u64*)(W_ih + (HH + j4)     * DIN + 16 * c4);
        const u64* pn = (const u64*)(W_ih + (2 * HH + j4) * DIN + 16 * c4);
        #pragma unroll
        for (int i = 0; i < 8; i++) { wihr[i] = pr[i]; wihz[i] = pz[i]; wihn[i] = pn[i]; }
    }
    u64 wout2[8];                                  // W_out[oo][16cc .. +16)
    {
        const u64* p = (const u64*)(W_out + oo * HH + 16 * cc);
        #pragma unroll
        for (int i = 0; i < 8; i++) wout2[i] = p[i];
    }

    // ---- biases / state ----
    const float bn  = b_node[j4];
    const float br  = b_ih[j4] + b_hh[j4];
    const float bz  = b_ih[HH + j4] + b_hh[HH + j4];
    const float bin = b_ih[2 * HH + j4];
    const float bhn = b_hh[2 * HH + j4];
    const float bout = b_out[oo];

    float lastout0 = bout, lastout1 = bout;        // out(h0=0) = b_out
    float xreg0 = 0.f, xreg1 = 0.f;
    if (cc == 0) {
        xreg0 = x[(2 * bid)     * TT * DIN + oo];
        xreg1 = x[(2 * bid + 1) * TT * DIN + oo];
    }
    float hbase = 0.f, hodev = 0.f, ksum = 0.f;
    if (t < 256) h_sm[t] = 0.f;
    __syncthreads();

    // node matvec partials (both samples, this lane's 32-k chunk)
    auto mvp = [&](const float* src, float& d0, float& d1) {
        const ulonglong2* q0 = (const ulonglong2*)(src)      + 8 * c4;
        const ulonglong2* q1 = (const ulonglong2*)(src + HH) + 8 * c4;
        u64 a0 = 0, a1 = 0, b0 = 0, b1 = 0;
        #pragma unroll
        for (int p = 0; p < 8; p++) {
            ulonglong2 v0 = q0[p], v1 = q1[p];
            a0 = f2fma(wn2[2*p],   v0.x, a0);
            a1 = f2fma(wn2[2*p+1], v0.y, a1);
            b0 = f2fma(wn2[2*p],   v1.x, b0);
            b1 = f2fma(wn2[2*p+1], v1.y, b1);
        }
        d0 = f2red(f2add(a0, a1));
        d1 = f2red(f2add(b0, b1));
    };

    for (int st = 0; st < TT; st++) {
        const float dt  = sdts[st];
        const float hdt = 0.5f * dt;
        const float dt6 = dt * (1.0f / 6.0f);

        // ---- P1: inp write + mv(k1) ----
        if (cc == 0) {
            bool m = (smask[st] != 0);
            inp_sm[oo]       = m ? xreg0 : lastout0;
            inp_sm[DIN + oo] = m ? xreg1 : lastout1;
            if (st + 1 < TT) {                      // reload for next step
                xreg0 = x[((2 * bid)     * TT + st + 1) * DIN + oo];
                xreg1 = x[((2 * bid + 1) * TT + st + 1) * DIN + oo];
            }
        }
        float d0, d1;
        mvp(h_sm, d0, d1);
        d0 += __shfl_xor_sync(0xFFFFFFFFu, d0, 1);
        d0 += __shfl_xor_sync(0xFFFFFFFFu, d0, 2);
        d1 += __shfl_xor_sync(0xFFFFFFFFu, d1, 1);
        d1 += __shfl_xor_sync(0xFFFFFFFFu, d1, 2);
        if (isw) {
            float k = tanh_mufu((sW ? d1 : d0) + bn);
            ksum = k;
            htmp_sm[sW * HH + j4] = hbase + hdt * k;
        }
        __syncthreads();

        // ---- k2 ----
        mvp(htmp_sm, d0, d1);
        d0 += __shfl_xor_sync(0xFFFFFFFFu, d0, 1);
        d0 += __shfl_xor_sync(0xFFFFFFFFu, d0, 2);
        d1 += __shfl_xor_sync(0xFFFFFFFFu, d1, 1);
        d1 += __shfl_xor_sync(0xFFFFFFFFu, d1, 2);
        if (isw) {
            float k = tanh_mufu((sW ? d1 : d0) + bn);
            ksum += 2.f * k;
            htmp_sm[sW * HH + j4] = hbase + hdt * k;
        }
        __syncthreads();

        // ---- k3 ----
        mvp(htmp_sm, d0, d1);
        d0 += __shfl_xor_sync(0xFFFFFFFFu, d0, 1);
        d0 += __shfl_xor_sync(0xFFFFFFFFu, d0, 2);
        d1 += __shfl_xor_sync(0xFFFFFFFFu, d1, 1);
        d1 += __shfl_xor_sync(0xFFFFFFFFu, d1, 2);
        if (isw) {
            float k = tanh_mufu((sW ? d1 : d0) + bn);
            ksum += 2.f * k;
            htmp_sm[sW * HH + j4] = hbase + dt * k;
        }
        __syncthreads();

        // ---- k4 -> h_ode ----
        mvp(htmp_sm, d0, d1);
        d0 += __shfl_xor_sync(0xFFFFFFFFu, d0, 1);
        d0 += __shfl_xor_sync(0xFFFFFFFFu, d0, 2);
        d1 += __shfl_xor_sync(0xFFFFFFFFu, d1, 1);
        d1 += __shfl_xor_sync(0xFFFFFFFFu, d1, 2);
        if (isw) {
            float k = tanh_mufu((sW ? d1 : d0) + bn);
            hodev = hbase + dt6 * (ksum + k);
            hode_sm[sW * HH + j4] = hodev;
        }
        __syncthreads();

        // ---- GRU: gate partials + 4-lane butterfly + in-lane combine ----
        {
            const ulonglong2* W2 = (const ulonglong2*)Whh_s;
            const ulonglong2* H0 = (const ulonglong2*)(hode_sm)      + 8 * c4;
            const ulonglong2* H1 = (const ulonglong2*)(hode_sm + HH) + 8 * c4;
            const int base = j4 * 4 + c4;
            u64 rA = 0, rB = 0, zA = 0, zB = 0, nA = 0, nB = 0;
            #pragma unroll
            for (int iq = 0; iq < 8; iq++) {
                ulonglong2 wr = W2[base + iq * 1536];
                ulonglong2 wz = W2[base + iq * 1536 + 512];
                ulonglong2 wn = W2[base + iq * 1536 + 1024];
                ulonglong2 h0 = H0[iq], h1 = H1[iq];
                rA = f2fma(wr.x, h0.x, rA); rA = f2fma(wr.y, h0.y, rA);
                rB = f2fma(wr.x, h1.x, rB); rB = f2fma(wr.y, h1.y, rB);
                zA = f2fma(wz.x, h0.x, zA); zA = f2fma(wz.y, h0.y, zA);
                zB = f2fma(wz.x, h1.x, zB); zB = f2fma(wz.y, h1.y, zB);
                nA = f2fma(wn.x, h0.x, nA); nA = f2fma(wn.y, h0.y, nA);
                nB = f2fma(wn.x, h1.x, nB); nB = f2fma(wn.y, h1.y, nB);
            }
            const u64* in0 = (const u64*)inp_sm + 8 * c4;
            const u64* in1 = in0 + 32;
            u64 iA = 0, iB = 0;
            #pragma unroll
            for (int p = 0; p < 8; p++) {
                u64 a = in0[p], b = in1[p];
                rA = f2fma(wihr[p], a, rA);
                zA = f2fma(wihz[p], a, zA);
                iA = f2fma(wihn[p], a, iA);
                rB = f2fma(wihr[p], b, rB);
                zB = f2fma(wihz[p], b, zB);
                iB = f2fma(wihn[p], b, iB);
            }
            float fr0 = f2red(rA), fr1 = f2red(rB);
            float fz0 = f2red(zA), fz1 = f2red(zB);
            float fi0 = f2red(iA), fi1 = f2red(iB);
            float fn0 = f2red(nA), fn1 = f2red(nB);
            #pragma unroll
            for (int m = 1; m <= 2; m <<= 1) {
                fr0 += __shfl_xor_sync(0xFFFFFFFFu, fr0, m);
                fr1 += __shfl_xor_sync(0xFFFFFFFFu, fr1, m);
                fz0 += __shfl_xor_sync(0xFFFFFFFFu, fz0, m);
                fz1 += __shfl_xor_sync(0xFFFFFFFFu, fz1, m);
                fi0 += __shfl_xor_sync(0xFFFFFFFFu, fi0, m);
                fi1 += __shfl_xor_sync(0xFFFFFFFFu, fi1, m);
                fn0 += __shfl_xor_sync(0xFFFFFFFFu, fn0, m);
                fn1 += __shfl_xor_sync(0xFFFFFFFFu, fn1, m);
            }
            if (isw) {
                float fr = sW ? fr1 : fr0, fz = sW ? fz1 : fz0;
                float fi = sW ? fi1 : fi0, fn = sW ? fn1 : fn0;
                float r = sigm(fr + br);
                float z = sigm(fz + bz);
                float n = tanhf(fi + bin + r * (fn + bhn));
                float hnew = (1.f - z) * n + z * hodev;
                hbase = hnew;
                h_sm[sW * HH + j4] = hnew;
            }
        }
        __syncthreads();

        // ---- OUT: out[st] = h_st @ W_out^T + b_out (own phase, no barrier) ----
        {
            const ulonglong2* hq0 = (const ulonglong2*)(h_sm)      + 4 * cc;
            const ulonglong2* hq1 = (const ulonglong2*)(h_sm + HH) + 4 * cc;
            u64 a0 = 0, a1 = 0, b0 = 0, b1 = 0;
            #pragma unroll
            for (int p = 0; p < 4; p++) {
                ulonglong2 v = hq0[p], w = hq1[p];
                a0 = f2fma(wout2[2*p],   v.x, a0);
                a1 = f2fma(wout2[2*p+1], v.y, a1);
                b0 = f2fma(wout2[2*p],   w.x, b0);
                b1 = f2fma(wout2[2*p+1], w.y, b1);
            }
            float o0 = f2red(f2add(a0, a1));
            float o1 = f2red(f2add(b0, b1));
            #pragma unroll
            for (int m = 1; m <= 4; m <<= 1) {
                o0 += __shfl_xor_sync(0xFFFFFFFFu, o0, m);
                o1 += __shfl_xor_sync(0xFFFFFFFFu, o1, m);
            }
            if (cc == 0) {
                float v0 = o0 + bout, v1 = o1 + bout;
                out[((2 * bid)     * TT + st) * DIN + oo] = v0;
                out[((2 * bid + 1) * TT + st) * DIN + oo] = v1;
                lastout0 = v0; lastout1 = v1;
            }
        }
    }
}

extern "C" void kernel_launch(void* const* d_in, const int* in_sizes, int n_in,
                              void* d_out, int out_size)
{
    (void)in_sizes; (void)n_in; (void)out_size;
    const float* x       = (const float*)d_in[0];
    const float* tp      = (const float*)d_in[1];
    const unsigned char* mask = (const unsigned char*)d_in[2];
    const float* W_ih    = (const float*)d_in[3];
    const float* W_hh    = (const float*)d_in[4];
    const float* b_ih    = (const float*)d_in[5];
    const float* b_hh    = (const float*)d_in[6];
    const float* W_node  = (const float*)d_in[7];
    const float* b_node  = (const float*)d_in[8];
    const float* W_out   = (const float*)d_in[9];
    const float* b_out   = (const float*)d_in[10];
    float* out = (float*)d_out;

    prep_kernel<<<192, 256>>>(W_hh, tp, mask);

    cudaFuncSetAttribute(gruode_kernel,
                         cudaFuncAttributeMaxDynamicSharedMemorySize, SMEM_BYTES);
    gruode_kernel<<<128, 512, SMEM_BYTES>>>(x, W_ih, b_ih, b_hh, W_node, b_node,
                                            W_out, b_out, out);
}